// round 1
// baseline (speedup 1.0000x reference)
#include <cuda_runtime.h>

#define BATCH 4
#define NPTS  4096
#define KNB   20
#define EPSV  1e-5f
#define SLOPE 0.2f

#define PTS 16              // points per block
#define EDG (PTS * KNB)     // 320 edges per block
#define THR 256

// scratch (device globals; no allocations allowed)
__device__ float g_wp[384 * 64];          // reindexed + s1-folded w1: Wp[m*6+c][o]
__device__ float g_w0f[384];              // s0-folded w0
__device__ int   g_idx[BATCH * NPTS * KNB];

__device__ __forceinline__ float lrelu(float v) { return fmaxf(v, SLOPE * v); }

__device__ __forceinline__ float2 ffma2(float2 a, float2 b, float2 c) {
    float2 d;
    asm("fma.rn.f32x2 %0, %1, %2, %3;"
        : "=l"(reinterpret_cast<unsigned long long&>(d))
        : "l"(reinterpret_cast<unsigned long long&>(a)),
          "l"(reinterpret_cast<unsigned long long&>(b)),
          "l"(reinterpret_cast<unsigned long long&>(c)));
    return d;
}
__device__ __forceinline__ float2 fmul2(float2 a, float2 b) {
    float2 d;
    asm("mul.rn.f32x2 %0, %1, %2;"
        : "=l"(reinterpret_cast<unsigned long long&>(d))
        : "l"(reinterpret_cast<unsigned long long&>(a)),
          "l"(reinterpret_cast<unsigned long long&>(b)));
    return d;
}

// ---------------------------------------------------------------------------
// Prep: fold BN scales into weights; reindex w1 (384,64) -> Wp[m*6+c][o]
// ---------------------------------------------------------------------------
__global__ void prep_kernel(const float* __restrict__ w0, const float* __restrict__ g0,
                            const float* __restrict__ w1, const float* __restrict__ g1) {
    int i = blockIdx.x * blockDim.x + threadIdx.x;
    const float inv = rsqrtf(1.f + EPSV);
    if (i < 384) g_w0f[i] = w0[i] * g0[i / 6] * inv;
    if (i < 384 * 64) {
        int o  = i & 63;
        int kc = i >> 6;        // m*6+c
        int m  = kc / 6;
        int c  = kc - m * 6;
        g_wp[i] = g1[o] * inv * w1[(o * 6 + c) * 64 + m];
    }
}

// ---------------------------------------------------------------------------
// KNN: per-thread brute-force top-20 (smallest ||xi-xj||^2, same formula as
// reference: xx_i + xx_j - 2*dot, self included since d_ii ~ 0 is minimal).
// Neighbor ORDER is irrelevant downstream (max over k).
// ---------------------------------------------------------------------------
__global__ void knn_kernel(const float* __restrict__ x) {
    const int b = blockIdx.y;
    const int q = blockIdx.x * 128 + threadIdx.x;
    const float* xb = x + b * 3 * NPTS;

    const float qx = xb[q], qy = xb[NPTS + q], qz = xb[2 * NPTS + q];
    const float qq = qx * qx + qy * qy + qz * qz;

    __shared__ float sx[128], sy[128], sz[128], ss[128];

    float nd[KNB];
    int   ni[KNB];
#pragma unroll
    for (int i = 0; i < KNB; i++) { nd[i] = __int_as_float(0x7f800000); ni[i] = 0; }
    float worst = __int_as_float(0x7f800000);
    int   wpos  = 0;

    for (int j0 = 0; j0 < NPTS; j0 += 128) {
        __syncthreads();
        const int t = threadIdx.x;
        float vx = xb[j0 + t], vy = xb[NPTS + j0 + t], vz = xb[2 * NPTS + j0 + t];
        sx[t] = vx; sy[t] = vy; sz[t] = vz;
        ss[t] = vx * vx + vy * vy + vz * vz;
        __syncthreads();

        for (int jj = 0; jj < 128; jj++) {
            float dot = fmaf(qx, sx[jj], fmaf(qy, sy[jj], qz * sz[jj]));
            float d   = fmaf(-2.f, dot, qq + ss[jj]);
            if (d < worst) {
                nd[wpos] = d; ni[wpos] = j0 + jj;
                worst = nd[0]; wpos = 0;
#pragma unroll
                for (int i = 1; i < KNB; i++)
                    if (nd[i] > worst) { worst = nd[i]; wpos = i; }
            }
        }
    }

    int* op = g_idx + (b * NPTS + q) * KNB;
#pragma unroll
    for (int i = 0; i < KNB; i++) op[i] = ni[i];
}

// ---------------------------------------------------------------------------
// Fused main kernel: feat gather -> y1 (6->64 conv+BN+LReLU) -> packed-f32x2
// GEMM (E x 384) @ (384 x 64) -> BN+LReLU -> max over k -> 64->3 conv+BN+LReLU
// Block = 16 points (320 edges). 256 threads: 32 edge-groups x 8 out-groups,
// each thread: 10 edges (5 f32x2 pairs) x 8 outs = 40 packed accumulators.
// ---------------------------------------------------------------------------
__global__ void __launch_bounds__(THR, 1) main_kernel(
    const float* __restrict__ x,    const float* __restrict__ b0,
    const float* __restrict__ b1,   const float* __restrict__ w_out,
    const float* __restrict__ g_out, const float* __restrict__ b_out,
    float* __restrict__ out)
{
    extern __shared__ float smem[];
    float* Wp  = smem;                 // 24576  Wp[kc][64]
    float* y1s = smem + 24576;         // 20480  y1s[m][320]
    float* fts = y1s + 20480;          //  1920  fts[c][320]
    float* x1s = fts + 1920;           //  1024  x1s[pt][64]
    float* w0f = x1s + 1024;           //   384
    float* b0s = w0f + 384;            //    64
    float* b1s = b0s + 64;             //    64

    const int tid = threadIdx.x;
    const int b   = blockIdx.x >> 8;            // 256 tiles per batch
    const int p0  = (blockIdx.x & 255) * PTS;
    const float* xb = x + b * 3 * NPTS;

    // load Wp (hot in L2 across blocks)
    {
        const float4* src = reinterpret_cast<const float4*>(g_wp);
        float4* dst = reinterpret_cast<float4*>(Wp);
#pragma unroll
        for (int i = 0; i < 24; i++) dst[tid + i * THR] = src[tid + i * THR];
    }
    for (int i = tid; i < 384; i += THR) w0f[i] = g_w0f[i];
    if (tid < 64) { b0s[tid] = b0[tid]; b1s[tid] = b1[tid]; }

    // gather feat: [xj - xi ; xi]
    for (int e = tid; e < EDG; e += THR) {
        int p  = e / KNB;
        int kk = e - p * KNB;
        int n  = p0 + p;
        int j  = g_idx[(b * NPTS + n) * KNB + kk];
        float xi0 = xb[n],          xi1 = xb[NPTS + n],  xi2 = xb[2 * NPTS + n];
        float xj0 = xb[j],          xj1 = xb[NPTS + j],  xj2 = xb[2 * NPTS + j];
        fts[0 * EDG + e] = xj0 - xi0;
        fts[1 * EDG + e] = xj1 - xi1;
        fts[2 * EDG + e] = xj2 - xi2;
        fts[3 * EDG + e] = xi0;
        fts[4 * EDG + e] = xi1;
        fts[5 * EDG + e] = xi2;
    }
    __syncthreads();

    // y1 = lrelu(w0f @ feat + b0)   (s0 already folded into w0f)
    for (int i = tid; i < 64 * EDG; i += THR) {
        int m = i / EDG;
        int e = i - m * EDG;
        const float* wr = w0f + m * 6;
        float v = b0s[m];
        v = fmaf(wr[0], fts[e],           v);
        v = fmaf(wr[1], fts[EDG + e],     v);
        v = fmaf(wr[2], fts[2 * EDG + e], v);
        v = fmaf(wr[3], fts[3 * EDG + e], v);
        v = fmaf(wr[4], fts[4 * EDG + e], v);
        v = fmaf(wr[5], fts[5 * EDG + e], v);
        y1s[i] = lrelu(v);
    }
    __syncthreads();

    const int og = tid & 7;       // 8 output groups
    const int eg = tid >> 3;      // 32 edge groups
    const int e0 = eg * 10;       // 10 edges -> 5 f32x2 pairs (all in point eg>>1)
    const int o0 = og * 8;        // 8 output channels

    float2 acc[5][8];
#pragma unroll
    for (int i = 0; i < 5; i++)
#pragma unroll
        for (int j = 0; j < 8; j++) acc[i][j] = make_float2(0.f, 0.f);

    // main GEMM: z[e][o] = sum_{m,c} (y1[e][m]*feat[e][c]) * Wp[m*6+c][o]
#pragma unroll 1
    for (int m = 0; m < 64; m++) {
        float2 yp[5];
        const float* yr = y1s + m * EDG + e0;
#pragma unroll
        for (int i = 0; i < 5; i++)
            yp[i] = *reinterpret_cast<const float2*>(yr + 2 * i);
#pragma unroll
        for (int c = 0; c < 6; c++) {
            const float* wr = Wp + (m * 6 + c) * 64 + o0;
            float4 wa = *reinterpret_cast<const float4*>(wr);
            float4 wb = *reinterpret_cast<const float4*>(wr + 4);
            float2 wd[8];
            wd[0] = make_float2(wa.x, wa.x); wd[1] = make_float2(wa.y, wa.y);
            wd[2] = make_float2(wa.z, wa.z); wd[3] = make_float2(wa.w, wa.w);
            wd[4] = make_float2(wb.x, wb.x); wd[5] = make_float2(wb.y, wb.y);
            wd[6] = make_float2(wb.z, wb.z); wd[7] = make_float2(wb.w, wb.w);
            const float* fr = fts + c * EDG + e0;
#pragma unroll
            for (int i = 0; i < 5; i++) {
                float2 fp = *reinterpret_cast<const float2*>(fr + 2 * i);
                float2 a  = fmul2(yp[i], fp);
#pragma unroll
                for (int j = 0; j < 8; j++)
                    acc[i][j] = ffma2(a, wd[j], acc[i][j]);
            }
        }
    }

    // epilogue: +b1, LReLU, max over the thread's 10 edges (all one point)
    float pmax[8];
#pragma unroll
    for (int j = 0; j < 8; j++) pmax[j] = -3.4e38f;
#pragma unroll
    for (int j = 0; j < 8; j++) {
        float bb = b1s[o0 + j];
#pragma unroll
        for (int i = 0; i < 5; i++) {
            float vx = lrelu(acc[i][j].x + bb);
            float vy = lrelu(acc[i][j].y + bb);
            pmax[j] = fmaxf(pmax[j], fmaxf(vx, vy));
        }
    }
    const int pt = eg >> 1;       // two threads (even/odd eg) per (pt, o-range)
    if ((eg & 1) == 0) {
#pragma unroll
        for (int j = 0; j < 8; j++) x1s[pt * 64 + o0 + j] = pmax[j];
    }
    __syncthreads();
    if (eg & 1) {
#pragma unroll
        for (int j = 0; j < 8; j++) {
            float* p = x1s + pt * 64 + o0 + j;
            *p = fmaxf(*p, pmax[j]);
        }
    }
    __syncthreads();

    // final conv: out = lrelu(s_out * (w_out @ x1) + b_out)
    if (tid < 48) {
        int oo  = tid >> 4;       // 0..2
        int pt2 = tid & 15;       // 0..15
        const float* wr = w_out + oo * 64;
        const float* xr = x1s + pt2 * 64;
        float s = 0.f;
#pragma unroll
        for (int o = 0; o < 64; o++) s = fmaf(wr[o], xr[o], s);
        float v = s * (g_out[oo] * rsqrtf(1.f + EPSV)) + b_out[oo];
        out[(b * 3 + oo) * NPTS + p0 + pt2] = lrelu(v);
    }
}

// ---------------------------------------------------------------------------
extern "C" void kernel_launch(void* const* d_in, const int* in_sizes, int n_in,
                              void* d_out, int out_size) {
    const float* x     = (const float*)d_in[0];
    const float* w0    = (const float*)d_in[1];
    const float* g0    = (const float*)d_in[2];
    const float* b0    = (const float*)d_in[3];
    const float* w1    = (const float*)d_in[4];
    const float* g1    = (const float*)d_in[5];
    const float* b1    = (const float*)d_in[6];
    const float* w_out = (const float*)d_in[7];
    const float* g_out = (const float*)d_in[8];
    const float* b_out = (const float*)d_in[9];
    float* out = (float*)d_out;

    const int smem_bytes = (24576 + 20480 + 1920 + 1024 + 384 + 64 + 64) * 4; // 194048

    prep_kernel<<<96, 256>>>(w0, g0, w1, g1);
    knn_kernel<<<dim3(NPTS / 128, BATCH), 128>>>(x);
    cudaFuncSetAttribute(main_kernel, cudaFuncAttributeMaxDynamicSharedMemorySize,
                         smem_bytes);
    main_kernel<<<BATCH * (NPTS / PTS), THR, smem_bytes>>>(x, b0, b1, w_out,
                                                           g_out, b_out, out);
}

// round 2
// speedup vs baseline: 1.1209x; 1.1209x over previous
#include <cuda_runtime.h>

#define BATCH 4
#define NPTS  4096
#define KNB   20
#define EPSV  1e-5f
#define SLOPE 0.2f

#define PTS 16              // points per block (main kernel)
#define EDG (PTS * KNB)     // 320 edges per block
#define THR 256

#define QPB 128             // queries per knn block (2 threads each)

// scratch (device globals; no allocations allowed)
__device__ float g_wp[384 * 64];          // reindexed + s1-folded w1: Wp[m*6+c][o]
__device__ float g_w0f[384];              // s0-folded w0
__device__ int   g_idx[BATCH * NPTS * KNB];

__device__ __forceinline__ float lrelu(float v) { return fmaxf(v, SLOPE * v); }

__device__ __forceinline__ float2 ffma2(float2 a, float2 b, float2 c) {
    float2 d;
    asm("fma.rn.f32x2 %0, %1, %2, %3;"
        : "=l"(reinterpret_cast<unsigned long long&>(d))
        : "l"(reinterpret_cast<unsigned long long&>(a)),
          "l"(reinterpret_cast<unsigned long long&>(b)),
          "l"(reinterpret_cast<unsigned long long&>(c)));
    return d;
}
__device__ __forceinline__ float2 fmul2(float2 a, float2 b) {
    float2 d;
    asm("mul.rn.f32x2 %0, %1, %2;"
        : "=l"(reinterpret_cast<unsigned long long&>(d))
        : "l"(reinterpret_cast<unsigned long long&>(a)),
          "l"(reinterpret_cast<unsigned long long&>(b)));
    return d;
}

// ---------------------------------------------------------------------------
// KNN (2-way split per query) + fused weight prep.
// Grid: (NPTS/QPB, BATCH) = (32, 4), 256 threads.
// Thread (half, tq): half = tid>>7 scans candidate range [half*2048, +2048)
// for query q = blockIdx.x*QPB + tq, keeping a register top-20 (smallest
// d' = ||p||^2 - 2 q.p ; the constant ||q||^2 shift preserves ordering, same
// as reference's -||q-p||^2 top_k, self point included). Half 1 dumps its
// list to smem; half 0 merges (top-20 of the union of two top-20s == global
// top-20). Neighbor ORDER is irrelevant downstream (max over k).
// Prep portion: fold BN scales into w0/w1, reindex w1 -> Wp[m*6+c][o].
// ---------------------------------------------------------------------------
__global__ void __launch_bounds__(256, 1) knn_prep_kernel(
    const float* __restrict__ x,
    const float* __restrict__ w0, const float* __restrict__ g0,
    const float* __restrict__ w1, const float* __restrict__ g1)
{
    // ---- prep: distributed over the 128 blocks ----
    {
        const int bid = blockIdx.y * gridDim.x + blockIdx.x;   // 0..127
        const int gt  = bid * 256 + threadIdx.x;               // 0..32767
        const float inv = rsqrtf(1.f + EPSV);
        if (gt < 384) g_w0f[gt] = w0[gt] * g0[gt / 6] * inv;
        if (gt < 384 * 64) {
            int o  = gt & 63;
            int kc = gt >> 6;        // m*6+c
            int m  = kc / 6;
            int c  = kc - m * 6;
            g_wp[gt] = g1[o] * inv * w1[(o * 6 + c) * 64 + m];
        }
    }

    // ---- knn ----
    const int tid  = threadIdx.x;
    const int tq   = tid & (QPB - 1);
    const int half = tid >> 7;            // 0 or 1
    const int b    = blockIdx.y;
    const int q    = blockIdx.x * QPB + tq;
    const float* xb = x + b * 3 * NPTS;

    const float qx = xb[q], qy = xb[NPTS + q], qz = xb[2 * NPTS + q];

    __shared__ float4 tile[2][128];           // (x,y,z,||p||^2)
    __shared__ float  mdist[QPB][KNB];        // half-1 results
    __shared__ int    midx [QPB][KNB];

    float nd[KNB];
    int   ni[KNB];
#pragma unroll
    for (int i = 0; i < KNB; i++) { nd[i] = __int_as_float(0x7f800000); ni[i] = 0; }
    float worst = __int_as_float(0x7f800000);
    int   wpos  = 0;

    const int base = half * 2048;
    for (int j0 = 0; j0 < 2048; j0 += 128) {
        __syncthreads();
        {
            const int t  = tid & 127;
            const int jg = base + j0 + t;
            float vx = xb[jg], vy = xb[NPTS + jg], vz = xb[2 * NPTS + jg];
            tile[half][t] = make_float4(vx, vy, vz,
                                        fmaf(vx, vx, fmaf(vy, vy, vz * vz)));
        }
        __syncthreads();

#pragma unroll 8
        for (int jj = 0; jj < 128; jj++) {
            float4 p  = tile[half][jj];
            float dot = fmaf(qx, p.x, fmaf(qy, p.y, qz * p.z));
            float d   = fmaf(-2.f, dot, p.w);
            if (d < worst) {
                nd[wpos] = d; ni[wpos] = base + j0 + jj;
                worst = nd[0]; wpos = 0;
#pragma unroll
                for (int i = 1; i < KNB; i++)
                    if (nd[i] > worst) { worst = nd[i]; wpos = i; }
            }
        }
    }

    __syncthreads();
    if (half == 1) {
#pragma unroll
        for (int i = 0; i < KNB; i++) { mdist[tq][i] = nd[i]; midx[tq][i] = ni[i]; }
    }
    __syncthreads();
    if (half == 0) {
#pragma unroll
        for (int i = 0; i < KNB; i++) {
            float d = mdist[tq][i];
            if (d < worst) {
                nd[wpos] = d; ni[wpos] = midx[tq][i];
                worst = nd[0]; wpos = 0;
#pragma unroll
                for (int t = 1; t < KNB; t++)
                    if (nd[t] > worst) { worst = nd[t]; wpos = t; }
            }
        }
        int* op = g_idx + (b * NPTS + q) * KNB;
#pragma unroll
        for (int i = 0; i < KNB; i++) op[i] = ni[i];
    }
}

// ---------------------------------------------------------------------------
// Fused main kernel: feat gather -> y1 (6->64 conv+BN+LReLU) -> packed-f32x2
// GEMM (E x 384) @ (384 x 64) -> BN+LReLU -> max over k -> 64->3 conv+BN+LReLU
// Block = 16 points (320 edges). 256 threads: 32 edge-groups x 8 out-groups,
// each thread: 10 edges (5 f32x2 pairs) x 8 outs = 40 packed accumulators.
// ---------------------------------------------------------------------------
__global__ void __launch_bounds__(THR, 1) main_kernel(
    const float* __restrict__ x,    const float* __restrict__ b0,
    const float* __restrict__ b1,   const float* __restrict__ w_out,
    const float* __restrict__ g_out, const float* __restrict__ b_out,
    float* __restrict__ out)
{
    extern __shared__ float smem[];
    float* Wp  = smem;                 // 24576  Wp[kc][64]
    float* y1s = smem + 24576;         // 20480  y1s[m][320]
    float* fts = y1s + 20480;          //  1920  fts[c][320]
    float* x1s = fts + 1920;           //  1024  x1s[pt][64]
    float* w0f = x1s + 1024;           //   384
    float* b0s = w0f + 384;            //    64
    float* b1s = b0s + 64;             //    64

    const int tid = threadIdx.x;
    const int b   = blockIdx.x >> 8;            // 256 tiles per batch
    const int p0  = (blockIdx.x & 255) * PTS;
    const float* xb = x + b * 3 * NPTS;

    // gather feat: [xj - xi ; xi]  (issue gmem-latency work first)
    for (int e = tid; e < EDG; e += THR) {
        int p  = e / KNB;
        int kk = e - p * KNB;
        int n  = p0 + p;
        int j  = g_idx[(b * NPTS + n) * KNB + kk];
        float xi0 = xb[n],          xi1 = xb[NPTS + n],  xi2 = xb[2 * NPTS + n];
        float xj0 = xb[j],          xj1 = xb[NPTS + j],  xj2 = xb[2 * NPTS + j];
        fts[0 * EDG + e] = xj0 - xi0;
        fts[1 * EDG + e] = xj1 - xi1;
        fts[2 * EDG + e] = xj2 - xi2;
        fts[3 * EDG + e] = xi0;
        fts[4 * EDG + e] = xi1;
        fts[5 * EDG + e] = xi2;
    }

    // load Wp (hot in L2 across blocks)
    {
        const float4* src = reinterpret_cast<const float4*>(g_wp);
        float4* dst = reinterpret_cast<float4*>(Wp);
#pragma unroll
        for (int i = 0; i < 24; i++) dst[tid + i * THR] = src[tid + i * THR];
    }
    for (int i = tid; i < 384; i += THR) w0f[i] = g_w0f[i];
    if (tid < 64) { b0s[tid] = b0[tid]; b1s[tid] = b1[tid]; }
    __syncthreads();

    // y1 = lrelu(w0f @ feat + b0)   (s0 already folded into w0f)
    for (int i = tid; i < 64 * EDG; i += THR) {
        int m = i / EDG;
        int e = i - m * EDG;
        const float* wr = w0f + m * 6;
        float v = b0s[m];
        v = fmaf(wr[0], fts[e],           v);
        v = fmaf(wr[1], fts[EDG + e],     v);
        v = fmaf(wr[2], fts[2 * EDG + e], v);
        v = fmaf(wr[3], fts[3 * EDG + e], v);
        v = fmaf(wr[4], fts[4 * EDG + e], v);
        v = fmaf(wr[5], fts[5 * EDG + e], v);
        y1s[i] = lrelu(v);
    }
    __syncthreads();

    const int og = tid & 7;       // 8 output groups
    const int eg = tid >> 3;      // 32 edge groups
    const int e0 = eg * 10;       // 10 edges -> 5 f32x2 pairs (all in point eg>>1)
    const int o0 = og * 8;        // 8 output channels

    float2 acc[5][8];
#pragma unroll
    for (int i = 0; i < 5; i++)
#pragma unroll
        for (int j = 0; j < 8; j++) acc[i][j] = make_float2(0.f, 0.f);

    // main GEMM: z[e][o] = sum_{m,c} (y1[e][m]*feat[e][c]) * Wp[m*6+c][o]
#pragma unroll 1
    for (int m = 0; m < 64; m++) {
        float2 yp[5];
        const float* yr = y1s + m * EDG + e0;
#pragma unroll
        for (int i = 0; i < 5; i++)
            yp[i] = *reinterpret_cast<const float2*>(yr + 2 * i);
#pragma unroll
        for (int c = 0; c < 6; c++) {
            const float* wr = Wp + (m * 6 + c) * 64 + o0;
            float4 wa = *reinterpret_cast<const float4*>(wr);
            float4 wb = *reinterpret_cast<const float4*>(wr + 4);
            float2 wd[8];
            wd[0] = make_float2(wa.x, wa.x); wd[1] = make_float2(wa.y, wa.y);
            wd[2] = make_float2(wa.z, wa.z); wd[3] = make_float2(wa.w, wa.w);
            wd[4] = make_float2(wb.x, wb.x); wd[5] = make_float2(wb.y, wb.y);
            wd[6] = make_float2(wb.z, wb.z); wd[7] = make_float2(wb.w, wb.w);
            const float* fr = fts + c * EDG + e0;
#pragma unroll
            for (int i = 0; i < 5; i++) {
                float2 fp = *reinterpret_cast<const float2*>(fr + 2 * i);
                float2 a  = fmul2(yp[i], fp);
#pragma unroll
                for (int j = 0; j < 8; j++)
                    acc[i][j] = ffma2(a, wd[j], acc[i][j]);
            }
        }
    }

    // epilogue: +b1, LReLU, max over the thread's 10 edges (all one point)
    float pmax[8];
#pragma unroll
    for (int j = 0; j < 8; j++) pmax[j] = -3.4e38f;
#pragma unroll
    for (int j = 0; j < 8; j++) {
        float bb = b1s[o0 + j];
#pragma unroll
        for (int i = 0; i < 5; i++) {
            float vx = lrelu(acc[i][j].x + bb);
            float vy = lrelu(acc[i][j].y + bb);
            pmax[j] = fmaxf(pmax[j], fmaxf(vx, vy));
        }
    }
    const int pt = eg >> 1;       // two threads (even/odd eg) per (pt, o-range)
    if ((eg & 1) == 0) {
#pragma unroll
        for (int j = 0; j < 8; j++) x1s[pt * 64 + o0 + j] = pmax[j];
    }
    __syncthreads();
    if (eg & 1) {
#pragma unroll
        for (int j = 0; j < 8; j++) {
            float* p = x1s + pt * 64 + o0 + j;
            *p = fmaxf(*p, pmax[j]);
        }
    }
    __syncthreads();

    // final conv: out = lrelu(s_out * (w_out @ x1) + b_out)
    if (tid < 48) {
        int oo  = tid >> 4;       // 0..2
        int pt2 = tid & 15;       // 0..15
        const float* wr = w_out + oo * 64;
        const float* xr = x1s + pt2 * 64;
        float s = 0.f;
#pragma unroll
        for (int o = 0; o < 64; o++) s = fmaf(wr[o], xr[o], s);
        float v = s * (g_out[oo] * rsqrtf(1.f + EPSV)) + b_out[oo];
        out[(b * 3 + oo) * NPTS + p0 + pt2] = lrelu(v);
    }
}

// ---------------------------------------------------------------------------
extern "C" void kernel_launch(void* const* d_in, const int* in_sizes, int n_in,
                              void* d_out, int out_size) {
    const float* x     = (const float*)d_in[0];
    const float* w0    = (const float*)d_in[1];
    const float* g0    = (const float*)d_in[2];
    const float* b0    = (const float*)d_in[3];
    const float* w1    = (const float*)d_in[4];
    const float* g1    = (const float*)d_in[5];
    const float* b1    = (const float*)d_in[6];
    const float* w_out = (const float*)d_in[7];
    const float* g_out = (const float*)d_in[8];
    const float* b_out = (const float*)d_in[9];
    float* out = (float*)d_out;

    const int smem_bytes = (24576 + 20480 + 1920 + 1024 + 384 + 64 + 64) * 4; // 194048

    knn_prep_kernel<<<dim3(NPTS / QPB, BATCH), 256>>>(x, w0, g0, w1, g1);
    cudaFuncSetAttribute(main_kernel, cudaFuncAttributeMaxDynamicSharedMemorySize,
                         smem_bytes);
    main_kernel<<<BATCH * (NPTS / PTS), THR, smem_bytes>>>(x, b0, b1, w_out,
                                                           g_out, b_out, out);
}